// round 15
// baseline (speedup 1.0000x reference)
#include <cuda_runtime.h>

#define NCL 127            // active clusters (reference excludes the last)
#define NPTS 1024
#define SLABS 16           // row slabs per cluster (64 rows each)
#define THREADS 128        // 4 warps; warp owns 16 rows
#define R 16               // rows per warp (broadcast across lanes)
#define BIGF 3.4e38f

__device__ float g_col[NCL * SLABS * NPTS];   // [c][slab][j] colmin partials
__device__ float g_rowsum[NCL * SLABS];
__device__ float g_cl[NCL];

// CTA = (cluster c, 64-row slab). Warp w owns rows slab*64 + w*16..+15 (row
// data broadcast in registers); lane owns column j = 32*s + lane at step s.
//   t(r,j) = fma(-2ax,bx, fma(-2ay,by, fma(-2az,bz, |b_j|^2)))   (3 FFMA)
//   d(r,j) = t + |a_r|^2
// Row-min: m[r] = fmin(m[r], t)  -- |a_r|^2 is constant over j, added after
//          the lane-merge (zero per-step adds on the row side).
// Col-min: running pairwise tree over (t + an[r]): 16 FADD + 15 FMNMX, one STS.
// Columns live in smem as float4 (x,y,z,|b|^2), staged coalesced via a raw
// float4 bounce through the wcol region.
__global__ void __launch_bounds__(THREADS, 5)
chamfer_main(const float* __restrict__ in_pts,
             const float* __restrict__ out_pts) {
    const int c    = blockIdx.x >> 4;
    const int slab = blockIdx.x & (SLABS - 1);

    const float* ap = in_pts  + (size_t)c * NPTS * 3;
    const float* bp = out_pts + (size_t)c * NPTS * 3;

    __shared__ float4 sb[NPTS];        // (x,y,z,|b|^2) per column, 16KB
    __shared__ float  wcol[4][NPTS];   // per-warp colmin per col, 16KB
    __shared__ float  redbuf[4];

    const int tid  = threadIdx.x;
    const int wid  = tid >> 5;
    const int lane = tid & 31;

    // Stage 1: raw coalesced copy of the 12KB column array into wcol space.
    {
        float4* wraw = (float4*)&wcol[0][0];          // 768 float4 = 12KB
        const float4* bp4 = (const float4*)bp;        // 16B-aligned (12288B rows)
#pragma unroll
        for (int k = 0; k < 6; k++)
            wraw[tid + 128 * k] = bp4[tid + 128 * k];
    }
    __syncthreads();

    // Stage 2: reformat 4 points (3 float4) at a time, computing norms.
    {
        const float4* wraw = (const float4*)&wcol[0][0];
#pragma unroll
        for (int k = 0; k < 2; k++) {
            int base = tid + 128 * k;                 // 3-float4 group index
            float4 f0 = wraw[3 * base + 0];
            float4 f1 = wraw[3 * base + 1];
            float4 f2 = wraw[3 * base + 2];
            // points: (f0.x f0.y f0.z) (f0.w f1.x f1.y) (f1.z f1.w f2.x) (f2.y f2.z f2.w)
            sb[4 * base + 0] = make_float4(f0.x, f0.y, f0.z,
                fmaf(f0.x, f0.x, fmaf(f0.y, f0.y, f0.z * f0.z)));
            sb[4 * base + 1] = make_float4(f0.w, f1.x, f1.y,
                fmaf(f0.w, f0.w, fmaf(f1.x, f1.x, f1.y * f1.y)));
            sb[4 * base + 2] = make_float4(f1.z, f1.w, f2.x,
                fmaf(f1.z, f1.z, fmaf(f1.w, f1.w, f2.x * f2.x)));
            sb[4 * base + 3] = make_float4(f2.y, f2.z, f2.w,
                fmaf(f2.y, f2.y, fmaf(f2.z, f2.z, f2.w * f2.w)));
        }
    }

    // This warp's 16 rows (192B, 16B-aligned): 12 uniform LDG.128.
    const float4* arow4 =
        (const float4*)(ap + ((size_t)slab * 64 + wid * R) * 3);
    float rf[48];
    {
        float4 rv[12];
#pragma unroll
        for (int k = 0; k < 12; k++) rv[k] = arow4[k];
#pragma unroll
        for (int k = 0; k < 12; k++) {
            rf[4 * k + 0] = rv[k].x;
            rf[4 * k + 1] = rv[k].y;
            rf[4 * k + 2] = rv[k].z;
            rf[4 * k + 3] = rv[k].w;
        }
    }
    float a2x[R], a2y[R], a2z[R], an[R], m[R];
#pragma unroll
    for (int r = 0; r < R; r++) {
        float x = rf[3 * r + 0];
        float y = rf[3 * r + 1];
        float z = rf[3 * r + 2];
        a2x[r] = -2.0f * x;
        a2y[r] = -2.0f * y;
        a2z[r] = -2.0f * z;
        an[r]  = fmaf(x, x, fmaf(y, y, z * z));
        m[r]   = BIGF;
    }
    __syncthreads();   // sb fully staged; wcol raw data dead from here on

    float* mycol = wcol[wid];

    // Main loop: 32 steps; lane's col j = 32*s + lane.
#pragma unroll 2
    for (int s = 0; s < NPTS / 32; s++) {
        float4 b = sb[(s << 5) | lane];
        float cm;
#pragma unroll
        for (int g = 0; g < 4; g++) {     // 4 rows per group, running tree
            float t0 = fmaf(a2x[4*g+0], b.x, fmaf(a2y[4*g+0], b.y, fmaf(a2z[4*g+0], b.z, b.w)));
            float t1 = fmaf(a2x[4*g+1], b.x, fmaf(a2y[4*g+1], b.y, fmaf(a2z[4*g+1], b.z, b.w)));
            m[4*g+0] = fminf(m[4*g+0], t0);
            m[4*g+1] = fminf(m[4*g+1], t1);
            float g0 = fminf(t0 + an[4*g+0], t1 + an[4*g+1]);
            float t2 = fmaf(a2x[4*g+2], b.x, fmaf(a2y[4*g+2], b.y, fmaf(a2z[4*g+2], b.z, b.w)));
            float t3 = fmaf(a2x[4*g+3], b.x, fmaf(a2y[4*g+3], b.y, fmaf(a2z[4*g+3], b.z, b.w)));
            m[4*g+2] = fminf(m[4*g+2], t2);
            m[4*g+3] = fminf(m[4*g+3], t3);
            float g1 = fminf(t2 + an[4*g+2], t3 + an[4*g+3]);
            float gg = fminf(g0, g1);
            cm = (g == 0) ? gg : fminf(cm, gg);
        }
        mycol[(s << 5) | lane] = cm;
    }

    // Row-min merge across lanes; add |a_r|^2 here (once per row).
    float rs = 0.0f;
#pragma unroll
    for (int r = 0; r < R; r++) {
        float v = m[r];
#pragma unroll
        for (int off = 16; off > 0; off >>= 1)
            v = fminf(v, __shfl_xor_sync(0xffffffffu, v, off));
        rs += v + an[r];
    }
    if (lane == 0) redbuf[wid] = rs;
    __syncthreads();

    // Col phase: merge 4 warps' colmins, store slab partial.
    float* gout = g_col + ((size_t)c * SLABS + slab) * NPTS;
    for (int col = tid; col < NPTS; col += THREADS) {
        float v = fminf(fminf(wcol[0][col], wcol[1][col]),
                        fminf(wcol[2][col], wcol[3][col]));
        gout[col] = v;
    }
    if (tid == 0)
        g_rowsum[blockIdx.x] =
            (redbuf[0] + redbuf[1]) + (redbuf[2] + redbuf[3]);
}

// Per-cluster: min colmin partials over 16 slabs, sum over cols, add row terms.
__global__ void cluster_reduce_kernel() {
    const int c   = blockIdx.x;      // 0..126
    const int tid = threadIdx.x;     // 256
    const float* base = g_col + (size_t)c * SLABS * NPTS;

    float s = 0.0f;
    for (int col = tid; col < NPTS; col += 256) {
        float v = BIGF;
#pragma unroll
        for (int sl = 0; sl < SLABS; sl++)
            v = fminf(v, base[sl * NPTS + col]);
        s += v;
    }
    if (tid < SLABS) s += g_rowsum[c * SLABS + tid];

#pragma unroll
    for (int off = 16; off > 0; off >>= 1)
        s += __shfl_down_sync(0xffffffffu, s, off);
    __shared__ float ws[8];
    if ((tid & 31) == 0) ws[tid >> 5] = s;
    __syncthreads();
    if (tid < 8) {
        s = ws[tid];
#pragma unroll
        for (int off = 4; off > 0; off >>= 1)
            s += __shfl_down_sync(0xffu, s, off);
        if (tid == 0) g_cl[c] = s;
    }
}

__global__ void final_sum_kernel(float* __restrict__ out) {
    const int tid = threadIdx.x;     // 128
    float s = (tid < NCL) ? g_cl[tid] : 0.0f;
#pragma unroll
    for (int off = 16; off > 0; off >>= 1)
        s += __shfl_down_sync(0xffffffffu, s, off);
    __shared__ float ws[4];
    if ((tid & 31) == 0) ws[tid >> 5] = s;
    __syncthreads();
    if (tid == 0) out[0] = (ws[0] + ws[1]) + (ws[2] + ws[3]);
}

extern "C" void kernel_launch(void* const* d_in, const int* in_sizes, int n_in,
                              void* d_out, int out_size) {
    const float* in_pts  = (const float*)d_in[0];
    const float* out_pts = (const float*)d_in[2];
    float* out = (float*)d_out;

    chamfer_main<<<NCL * SLABS, THREADS>>>(in_pts, out_pts);
    cluster_reduce_kernel<<<NCL, 256>>>();
    final_sum_kernel<<<1, 128>>>(out);
}

// round 17
// speedup vs baseline: 1.5322x; 1.5322x over previous
#include <cuda_runtime.h>

#define NCL 127            // active clusters (reference excludes the last)
#define NPTS 1024
#define SLABS 16           // row slabs per cluster (64 rows each)
#define THREADS 128        // 4 warps; warp owns 16 rows
#define R 16               // rows per warp (broadcast across lanes)
#define BIGF 3.4e38f

__device__ float g_col[NCL * SLABS * NPTS];   // [c][slab][j] colmin partials
__device__ float g_rowsum[NCL * SLABS];
__device__ float g_cl[NCL];

// CTA = (cluster c, 64-row slab). Warp w owns rows slab*64 + w*16..+15 (row
// data broadcast in registers); lane owns column j = 32*s + lane at step s.
//   t_r = fma(-2ax,bx, fma(-2ay,by, fma(-2az,bz, |a_r|^2)))   (3 FFMA)
//   d(r,j) = t_r + |b_j|^2
// Row-min: m[r] = fmin(m[r], t_r + bw)  (lane-private, shfl-merged at end)
// Col-min: (15-FMNMX tree over t_r) + bw, one STS per step.
// The next step's column float4 is prefetched into registers before the
// compute block so the 29-cyc LDS latency is hidden.
__global__ void __launch_bounds__(THREADS, 4)
chamfer_main(const float* __restrict__ in_pts,
             const float* __restrict__ out_pts) {
    const int c    = blockIdx.x >> 4;
    const int slab = blockIdx.x & (SLABS - 1);

    const float* ap = in_pts  + (size_t)c * NPTS * 3;
    const float* bp = out_pts + (size_t)c * NPTS * 3;

    __shared__ float4 sb[NPTS];        // (x,y,z,|b|^2) per column, 16KB
    __shared__ float  wcol[4][NPTS];   // per-warp colmin per col, 16KB
    __shared__ float  redbuf[4];

    const int tid  = threadIdx.x;
    const int wid  = tid >> 5;
    const int lane = tid & 31;

    // Stage columns + norms.
    for (int j = tid; j < NPTS; j += THREADS) {
        float x = bp[3 * j + 0];
        float y = bp[3 * j + 1];
        float z = bp[3 * j + 2];
        sb[j] = make_float4(x, y, z, fmaf(x, x, fmaf(y, y, z * z)));
    }

    // This warp's 16 rows (192B, 16B-aligned): 12 uniform LDG.128.
    const float4* arow4 =
        (const float4*)(ap + ((size_t)slab * 64 + wid * R) * 3);
    float rf[48];
    {
        float4 rv[12];
#pragma unroll
        for (int k = 0; k < 12; k++) rv[k] = arow4[k];
#pragma unroll
        for (int k = 0; k < 12; k++) {
            rf[4 * k + 0] = rv[k].x;
            rf[4 * k + 1] = rv[k].y;
            rf[4 * k + 2] = rv[k].z;
            rf[4 * k + 3] = rv[k].w;
        }
    }
    float a2x[R], a2y[R], a2z[R], an[R], m[R];
#pragma unroll
    for (int r = 0; r < R; r++) {
        float x = rf[3 * r + 0];
        float y = rf[3 * r + 1];
        float z = rf[3 * r + 2];
        a2x[r] = -2.0f * x;
        a2y[r] = -2.0f * y;
        a2z[r] = -2.0f * z;
        an[r]  = fmaf(x, x, fmaf(y, y, z * z));
        m[r]   = BIGF;
    }
    __syncthreads();

    const float4* sbl  = sb + lane;          // this lane's column stream
    float*        outp = wcol[wid] + lane;   // this lane's colmin stream

    // Main loop: 32 steps; lane's col j = 32*s + lane. Next b prefetched.
    float4 b = sbl[0];
    for (int s = 0; s < NPTS / 32; s++) {
        float4 bn = sbl[((s + 1) & 31) << 5];   // wraps at end; unused value

        float t[R];
#pragma unroll
        for (int r = 0; r < R; r++) {
            t[r] = fmaf(a2x[r], b.x,
                   fmaf(a2y[r], b.y,
                   fmaf(a2z[r], b.z, an[r])));
            m[r] = fminf(m[r], t[r] + b.w);
        }
        float c0 = fminf(fminf(t[0],  t[1]),  fminf(t[2],  t[3]));
        float c1 = fminf(fminf(t[4],  t[5]),  fminf(t[6],  t[7]));
        float c2 = fminf(fminf(t[8],  t[9]),  fminf(t[10], t[11]));
        float c3 = fminf(fminf(t[12], t[13]), fminf(t[14], t[15]));
        outp[s << 5] = fminf(fminf(c0, c1), fminf(c2, c3)) + b.w;
        b = bn;
    }

    // Row-min merge across lanes: butterfly per row, then sum over rows.
    float rs = 0.0f;
#pragma unroll
    for (int r = 0; r < R; r++) {
        float v = m[r];
#pragma unroll
        for (int off = 16; off > 0; off >>= 1)
            v = fminf(v, __shfl_xor_sync(0xffffffffu, v, off));
        rs += v;
    }
    if (lane == 0) redbuf[wid] = rs;
    __syncthreads();

    // Col phase: merge 4 warps' colmins, store slab partial.
    float* gout = g_col + ((size_t)c * SLABS + slab) * NPTS;
    for (int col = tid; col < NPTS; col += THREADS) {
        float v = fminf(fminf(wcol[0][col], wcol[1][col]),
                        fminf(wcol[2][col], wcol[3][col]));
        gout[col] = v;
    }
    if (tid == 0)
        g_rowsum[blockIdx.x] =
            (redbuf[0] + redbuf[1]) + (redbuf[2] + redbuf[3]);
}

// Per-cluster: min colmin partials over 16 slabs, sum over cols, add row terms.
__global__ void cluster_reduce_kernel() {
    const int c   = blockIdx.x;      // 0..126
    const int tid = threadIdx.x;     // 256
    const float* base = g_col + (size_t)c * SLABS * NPTS;

    float s = 0.0f;
    for (int col = tid; col < NPTS; col += 256) {
        float v = BIGF;
#pragma unroll
        for (int sl = 0; sl < SLABS; sl++)
            v = fminf(v, base[sl * NPTS + col]);
        s += v;
    }
    if (tid < SLABS) s += g_rowsum[c * SLABS + tid];

#pragma unroll
    for (int off = 16; off > 0; off >>= 1)
        s += __shfl_down_sync(0xffffffffu, s, off);
    __shared__ float ws[8];
    if ((tid & 31) == 0) ws[tid >> 5] = s;
    __syncthreads();
    if (tid < 8) {
        s = ws[tid];
#pragma unroll
        for (int off = 4; off > 0; off >>= 1)
            s += __shfl_down_sync(0xffu, s, off);
        if (tid == 0) g_cl[c] = s;
    }
}

__global__ void final_sum_kernel(float* __restrict__ out) {
    const int tid = threadIdx.x;     // 128
    float s = (tid < NCL) ? g_cl[tid] : 0.0f;
#pragma unroll
    for (int off = 16; off > 0; off >>= 1)
        s += __shfl_down_sync(0xffffffffu, s, off);
    __shared__ float ws[4];
    if ((tid & 31) == 0) ws[tid >> 5] = s;
    __syncthreads();
    if (tid == 0) out[0] = (ws[0] + ws[1]) + (ws[2] + ws[3]);
}

extern "C" void kernel_launch(void* const* d_in, const int* in_sizes, int n_in,
                              void* d_out, int out_size) {
    const float* in_pts  = (const float*)d_in[0];
    const float* out_pts = (const float*)d_in[2];
    float* out = (float*)d_out;

    chamfer_main<<<NCL * SLABS, THREADS>>>(in_pts, out_pts);
    cluster_reduce_kernel<<<NCL, 256>>>();
    final_sum_kernel<<<1, 128>>>(out);
}